// round 4
// baseline (speedup 1.0000x reference)
#include <cuda_runtime.h>
#include <math.h>

#define NN 50000
#define EE 800000
#define CC 64
#define SS 10
#define HH 64

typedef unsigned long long ull;

// -------- scratch (static device globals; no allocation) --------
__device__ float g_h0[NN * CC];        // up-projected scalars   [n][c]
__device__ float g_h1[NN * 3 * CC];    // up-projected vectors   [n][i][c]
__device__ float g_T0[NN * CC];        // node messages (already /16)
__device__ float g_T1[NN * 3 * CC];
__device__ int   g_deg[NN];
__device__ int   g_off[NN + 1];
__device__ int   g_cur[NN];
__device__ int   g_perm[EE];

// -------- f32x2 packed math helpers (sm_100+) --------
__device__ __forceinline__ ull dup2(float x) {
    ull r;
    asm("mov.b64 %0, {%1, %1};" : "=l"(r) : "r"(__float_as_uint(x)));
    return r;
}
__device__ __forceinline__ void fma2(ull& d, ull a, ull b) {
    asm("fma.rn.f32x2 %0, %1, %2, %0;" : "+l"(d) : "l"(a), "l"(b));
}
__device__ __forceinline__ ull mul2(ull a, ull b) {
    ull d;
    asm("mul.rn.f32x2 %0, %1, %2;" : "=l"(d) : "l"(a), "l"(b));
    return d;
}
__device__ __forceinline__ void unpack2(ull v, float& lo, float& hi) {
    unsigned int a, b;
    asm("mov.b64 {%0, %1}, %2;" : "=r"(a), "=r"(b) : "l"(v));
    lo = __uint_as_float(a);
    hi = __uint_as_float(b);
}

// ============================================================
// CSR build
// ============================================================
__global__ void zero_deg_kernel() {
    int i = blockIdx.x * 256 + threadIdx.x;
    if (i < NN) g_deg[i] = 0;
}

__global__ void hist_kernel(const int* __restrict__ ei) {
    int e = blockIdx.x * 256 + threadIdx.x;   // E = 3125*256 exact
    atomicAdd(&g_deg[ei[EE + e]], 1);
}

__global__ void __launch_bounds__(1024) scan_kernel() {
    __shared__ int sp[1024];
    const int t = threadIdx.x;
    const int CH = (NN + 1023) / 1024;       // 49
    const int i0 = t * CH;
    const int i1 = min(i0 + CH, NN);
    int part = 0;
    for (int i = i0; i < i1; i++) part += g_deg[i];
    sp[t] = part;
    __syncthreads();
    for (int off = 1; off < 1024; off <<= 1) {
        int v = (t >= off) ? sp[t - off] : 0;
        __syncthreads();
        sp[t] += v;
        __syncthreads();
    }
    int run = sp[t] - part;                  // exclusive base
    for (int i = i0; i < i1; i++) {
        g_off[i] = run;
        g_cur[i] = run;
        run += g_deg[i];
    }
    if (t == 0) g_off[NN] = EE;
}

__global__ void scatter_kernel(const int* __restrict__ ei) {
    int e = blockIdx.x * 256 + threadIdx.x;
    int pos = atomicAdd(&g_cur[ei[EE + e]], 1);
    g_perm[pos] = e;
}

// ============================================================
// Up-projection: h0 = nf0 @ Wup0 ; g_h1[n][i][o] = sum_c nf1[n,c,i] Wup1[c,o]
// ============================================================
__global__ void __launch_bounds__(256) up_kernel(
    const float* __restrict__ nf0, const float* __restrict__ nf1,
    const float* __restrict__ Wup0, const float* __restrict__ Wup1) {
    extern __shared__ float sm[];
    float* sW0  = sm;            // 4096
    float* sW1m = sm + 4096;     // 4096
    float* s0   = sm + 8192;     // 32*64
    float* s1   = sm + 10240;    // 32*192
    const int tid  = threadIdx.x;
    const int base = blockIdx.x * 32;

    for (int i = tid; i < 4096; i += 256) { sW0[i] = Wup0[i]; sW1m[i] = Wup1[i]; }
    for (int i = tid; i < 2048; i += 256) {
        size_t g = (size_t)base * 64 + i;
        s0[i] = (g < (size_t)NN * 64) ? nf0[g] : 0.f;
    }
    for (int i = tid; i < 6144; i += 256) {
        size_t g = (size_t)base * 192 + i;
        s1[i] = (g < (size_t)NN * 192) ? nf1[g] : 0.f;
    }
    __syncthreads();

    const int o = tid & 63, ng = tid >> 6;
    for (int nl = ng; nl < 32; nl += 4) {
        const int n = base + nl;
        if (n >= NN) break;
        float a = 0.f;
#pragma unroll
        for (int c = 0; c < 64; c++) a += s0[nl * 64 + c] * sW0[c * 64 + o];
        g_h0[(size_t)n * 64 + o] = a;
#pragma unroll
        for (int i3 = 0; i3 < 3; i3++) {
            float b = 0.f;
#pragma unroll 16
            for (int c = 0; c < 64; c++)
                b += s1[nl * 192 + c * 3 + i3] * sW1m[c * 64 + o];
            g_h1[((size_t)n * 3 + i3) * 64 + o] = b;
        }
    }
}

// ============================================================
// Fused node-centric kernel: warp per node, NJ-edge batches.
// Hidden stored pre-duplicated (f32x2) in smem; W2 GEMV amortizes
// smem reads over NJ edges; messages accumulate in registers.
// ============================================================
template<int NJ>
__device__ __forceinline__ void process_batch(
    const int b, const int end, const int lane,
    const float* __restrict__ sW1, const float* __restrict__ sW2,
    ull* __restrict__ sHd,
    const float* __restrict__ ef, const float* __restrict__ ea1,
    const float* __restrict__ cut, const int* __restrict__ ei,
    ull& m0, ull& m1x, ull& m1y, ull& m1z) {
    const unsigned FULL = 0xffffffffu;
    const int l2 = 2 * lane;

    // lanes 0..NJ-1 stage edge b+lane (padded slots: cu=0 kills contributions)
    int src_ = 0;
    float cu_ = 0.f, sx_ = 0.f, sy_ = 0.f, sz_ = 0.f;
    float4 f0_ = make_float4(0.f, 0.f, 0.f, 0.f), f1_ = f0_;
    if (lane < NJ) {
        const int idx = b + lane;
        const int ee  = g_perm[idx < end ? idx : b];
        src_ = ei[ee];
        cu_  = (idx < end) ? cut[ee] : 0.f;
        sx_  = ea1[ee * 3];
        sy_  = ea1[ee * 3 + 1];
        sz_  = ea1[ee * 3 + 2];
        f0_  = *(const float4*)(ef + (size_t)ee * 8);
        f1_  = *(const float4*)(ef + (size_t)ee * 8 + 4);
    }

    // hidden = silu(ef @ W1); lane computes units (2l, 2l+1) for each edge,
    // stores DUPLICATED (f32x2) so the GEMV can use broadcast loads directly.
#pragma unroll
    for (int j = 0; j < NJ; j++) {
        float fr[8];
        fr[0] = __shfl_sync(FULL, f0_.x, j);
        fr[1] = __shfl_sync(FULL, f0_.y, j);
        fr[2] = __shfl_sync(FULL, f0_.z, j);
        fr[3] = __shfl_sync(FULL, f0_.w, j);
        fr[4] = __shfl_sync(FULL, f1_.x, j);
        fr[5] = __shfl_sync(FULL, f1_.y, j);
        fr[6] = __shfl_sync(FULL, f1_.z, j);
        fr[7] = __shfl_sync(FULL, f1_.w, j);
        float a0 = 0.f, a1 = 0.f;
#pragma unroll
        for (int r = 0; r < 8; r++) {
            float2 wv = *(const float2*)(sW1 + r * 64 + l2);
            a0 = fmaf(fr[r], wv.x, a0);
            a1 = fmaf(fr[r], wv.y, a1);
        }
        a0 = a0 / (1.f + __expf(-a0));
        a1 = a1 / (1.f + __expf(-a1));
        *(ulonglong2*)(sHd + j * 64 + l2) = make_ulonglong2(dup2(a0), dup2(a1));
    }
    __syncwarp();

    // w = hid @ W2; lane owns channel pair (2l, 2l+1) of each of the 4 groups
    ull w00[NJ], w11[NJ], w01[NJ], w10[NJ];
#pragma unroll
    for (int j = 0; j < NJ; j++) { w00[j] = 0; w11[j] = 0; w01[j] = 0; w10[j] = 0; }
    const float* bp = sW2 + l2;
#pragma unroll 2
    for (int h = 0; h < 64; h += 2) {
        const float* r0 = bp + h * 256;
        const float* r1 = r0 + 256;
        const ull b00a = *(const ull*)r0,         b00b = *(const ull*)r1;
        const ull b11a = *(const ull*)(r0 + 64),  b11b = *(const ull*)(r1 + 64);
        const ull b01a = *(const ull*)(r0 + 128), b01b = *(const ull*)(r1 + 128);
        const ull b10a = *(const ull*)(r0 + 192), b10b = *(const ull*)(r1 + 192);
#pragma unroll
        for (int j = 0; j < NJ; j++) {
            const ulonglong2 ha = *(const ulonglong2*)(sHd + j * 64 + h);
            fma2(w00[j], ha.x, b00a); fma2(w00[j], ha.y, b00b);
            fma2(w11[j], ha.x, b11a); fma2(w11[j], ha.y, b11b);
            fma2(w01[j], ha.x, b01a); fma2(w01[j], ha.y, b01b);
            fma2(w10[j], ha.x, b10a); fma2(w10[j], ha.y, b10b);
        }
    }

    // combine messages (gathers streamed per edge)
#pragma unroll
    for (int j = 0; j < NJ; j++) {
        const int   sj  = __shfl_sync(FULL, src_, j);
        const float cub = __shfl_sync(FULL, cu_, j);
        const float sxb = __shfl_sync(FULL, sx_, j);
        const float syb = __shfl_sync(FULL, sy_, j);
        const float szb = __shfl_sync(FULL, sz_, j);
        const float* p0 = g_h0 + (size_t)sj * 64 + l2;
        const float* p1 = g_h1 + (size_t)sj * 192 + l2;
        const ull gh0 = *(const ull*)p0;
        const ull ghx = *(const ull*)p1;
        const ull ghy = *(const ull*)(p1 + 64);
        const ull ghz = *(const ull*)(p1 + 128);
        ull d = mul2(ghx, dup2(sxb));
        fma2(d, ghy, dup2(syb));
        fma2(d, ghz, dup2(szb));
        ull t = mul2(w00[j], gh0);
        fma2(t, w11[j], d);
        fma2(m0, t, dup2(cub));
        ull p = mul2(w01[j], gh0);
        fma2(m1x, p, dup2(cub * sxb));
        fma2(m1y, p, dup2(cub * syb));
        fma2(m1z, p, dup2(cub * szb));
        ull q = mul2(w10[j], dup2(cub));
        fma2(m1x, q, ghx);
        fma2(m1y, q, ghy);
        fma2(m1z, q, ghz);
    }
    __syncwarp();   // protect sHd before next batch overwrites
}

__global__ void __launch_bounds__(128, 2) node_kernel(
    const float* __restrict__ ef, const float* __restrict__ ea1,
    const float* __restrict__ cut, const float* __restrict__ W1,
    const float* __restrict__ W2, const int* __restrict__ ei) {
    extern __shared__ float sm[];
    float* sW1 = sm;                                  // 512 floats
    float* sW2 = sm + 512;                            // 16384 floats
    ull*   sHdAll = (ull*)(sm + 512 + 16384);         // 4 warps * 512 ull
    const int tid = threadIdx.x;
    for (int i = tid; i < 512; i += 128)   sW1[i] = W1[i];
    for (int i = tid; i < 16384; i += 128) sW2[i] = W2[i];
    __syncthreads();

    const int wid = tid >> 5, lane = tid & 31;
    ull* sHd = sHdAll + wid * 512;
    const int l2 = 2 * lane;

    for (int node = blockIdx.x * 4 + wid; node < NN; node += gridDim.x * 4) {
        const int beg = g_off[node];
        const int end = g_off[node + 1];
        ull m0 = 0, m1x = 0, m1y = 0, m1z = 0;

        int b = beg;
        for (; b + 8 <= end; b += 8)
            process_batch<8>(b, end, lane, sW1, sW2, sHd, ef, ea1, cut, ei,
                             m0, m1x, m1y, m1z);
        const int rem = end - b;
        if (rem > 4)
            process_batch<8>(b, end, lane, sW1, sW2, sHd, ef, ea1, cut, ei,
                             m0, m1x, m1y, m1z);
        else if (rem > 0)
            process_batch<4>(b, end, lane, sW1, sW2, sHd, ef, ea1, cut, ei,
                             m0, m1x, m1y, m1z);

        const ull inv = dup2(1.f / 16.f);
        *(ull*)(g_T0 + (size_t)node * 64 + l2) = mul2(m0, inv);
        float* t1 = g_T1 + (size_t)node * 192 + l2;
        *(ull*)t1         = mul2(m1x, inv);
        *(ull*)(t1 + 64)  = mul2(m1y, inv);
        *(ull*)(t1 + 128) = mul2(m1z, inv);
    }
}

// ============================================================
// Epilogue 0: out[n][0:64] = mi0 ; out[n][256:320] = mi0 @ Wsc0[s]
// ============================================================
__global__ void __launch_bounds__(256) node0_kernel(
    const float* __restrict__ attrs, const float* __restrict__ Wsc0,
    float* __restrict__ out) {
    extern __shared__ float sm[];
    float* sW  = sm;              // 40960
    float* sMi = sm + 40960;      // 8 warps * 64
    const int tid = threadIdx.x, wid = tid >> 5, lane = tid & 31;
    const int l2 = 2 * lane;
    const unsigned FULL = 0xffffffffu;
    for (int i = tid; i < SS * CC * CC; i += 256) sW[i] = Wsc0[i];
    __syncthreads();

    float* sMiW = sMi + wid * 64;
    for (int node = blockIdx.x * 8 + wid; node < NN; node += gridDim.x * 8) {
        const ull mi = *(const ull*)(g_T0 + (size_t)node * 64 + l2);
        *(ull*)(sMiW + l2) = mi;
        const float av = (lane < SS) ? attrs[(size_t)node * SS + lane] : 0.f;
        const unsigned bal = __ballot_sync(FULL, av > 0.5f);
        int s = __ffs(bal) - 1;
        if (s < 0) s = 0;
        __syncwarp();
        const float* W = sW + s * 4096 + l2;
        ull A = 0;
#pragma unroll 8
        for (int c = 0; c < 64; c++)
            fma2(A, dup2(sMiW[c]), *(const ull*)(W + c * 64));
        float* orow = out + (size_t)node * 512;
        *(ull*)(orow + l2)       = mi;
        *(ull*)(orow + 256 + l2) = A;
        __syncwarp();
    }
}

// ============================================================
// Epilogue 1: out[n][64+c*3+i] = mi1 ; out[n][320+o*3+i] = res1
// ============================================================
__global__ void __launch_bounds__(256) node1_kernel(
    const float* __restrict__ attrs, const float* __restrict__ Wsc1,
    float* __restrict__ out) {
    extern __shared__ float sm[];
    float* sW  = sm;              // 40960
    float* sMi = sm + 40960;      // 8 warps * 192
    const int tid = threadIdx.x, wid = tid >> 5, lane = tid & 31;
    const int l2 = 2 * lane;
    const unsigned FULL = 0xffffffffu;
    for (int i = tid; i < SS * CC * CC; i += 256) sW[i] = Wsc1[i];
    __syncthreads();

    float* sMiW = sMi + wid * 192;
    for (int node = blockIdx.x * 8 + wid; node < NN; node += gridDim.x * 8) {
        const float* t1 = g_T1 + (size_t)node * 192 + l2;
        const ull mx = *(const ull*)t1;
        const ull my = *(const ull*)(t1 + 64);
        const ull mz = *(const ull*)(t1 + 128);
        *(ull*)(sMiW + l2)        = mx;
        *(ull*)(sMiW + 64 + l2)   = my;
        *(ull*)(sMiW + 128 + l2)  = mz;
        const float av = (lane < SS) ? attrs[(size_t)node * SS + lane] : 0.f;
        const unsigned bal = __ballot_sync(FULL, av > 0.5f);
        int s = __ffs(bal) - 1;
        if (s < 0) s = 0;
        __syncwarp();
        const float* W = sW + s * 4096 + l2;
        ull A0 = 0, A1 = 0, A2 = 0;
#pragma unroll 8
        for (int c = 0; c < 64; c++) {
            const ull wv = *(const ull*)(W + c * 64);
            fma2(A0, dup2(sMiW[c]), wv);
            fma2(A1, dup2(sMiW[64 + c]), wv);
            fma2(A2, dup2(sMiW[128 + c]), wv);
        }
        float x0, x1, y0, y1, z0, z1;
        unpack2(mx, x0, x1); unpack2(my, y0, y1); unpack2(mz, z0, z1);
        float* orow = out + (size_t)node * 512;
        float* om = orow + 64 + 6 * lane;
        om[0] = x0; om[1] = y0; om[2] = z0;
        om[3] = x1; om[4] = y1; om[5] = z1;
        unpack2(A0, x0, x1); unpack2(A1, y0, y1); unpack2(A2, z0, z1);
        float* orr = orow + 320 + 6 * lane;
        orr[0] = x0; orr[1] = y0; orr[2] = z0;
        orr[3] = x1; orr[4] = y1; orr[5] = z1;
        __syncwarp();
    }
}

// ============================================================
extern "C" void kernel_launch(void* const* d_in, const int* in_sizes, int n_in,
                              void* d_out, int out_size) {
    const float* nf0   = (const float*)d_in[0];
    const float* nf1   = (const float*)d_in[1];
    const float* attrs = (const float*)d_in[2];
    const float* ef    = (const float*)d_in[3];
    const float* ea1   = (const float*)d_in[4];
    const float* cut   = (const float*)d_in[5];
    const float* Wup0  = (const float*)d_in[6];
    const float* Wup1  = (const float*)d_in[7];
    const float* W1    = (const float*)d_in[8];
    const float* W2    = (const float*)d_in[9];
    const float* Wsc0  = (const float*)d_in[10];
    const float* Wsc1  = (const float*)d_in[11];
    // d_in[12], d_in[13] are Q0/Q1 identity projectors (no-op)
    const int*   ei    = (const int*)d_in[14];
    float* out = (float*)d_out;

    const int up_smem   = 16384 * 4;                        // 64 KB
    const int node_smem = (512 + 16384) * 4 + 4 * 512 * 8;  // 84 KB
    const int c0_smem   = (40960 + 512) * 4;                // 166 KB
    const int c1_smem   = (40960 + 1536) * 4;               // 170 KB
    cudaFuncSetAttribute(up_kernel,    cudaFuncAttributeMaxDynamicSharedMemorySize, up_smem);
    cudaFuncSetAttribute(node_kernel,  cudaFuncAttributeMaxDynamicSharedMemorySize, node_smem);
    cudaFuncSetAttribute(node0_kernel, cudaFuncAttributeMaxDynamicSharedMemorySize, c0_smem);
    cudaFuncSetAttribute(node1_kernel, cudaFuncAttributeMaxDynamicSharedMemorySize, c1_smem);

    zero_deg_kernel<<<(NN + 255) / 256, 256>>>();
    hist_kernel<<<EE / 256, 256>>>(ei);
    scan_kernel<<<1, 1024>>>();
    scatter_kernel<<<EE / 256, 256>>>(ei);
    up_kernel<<<(NN + 31) / 32, 256, up_smem>>>(nf0, nf1, Wup0, Wup1);
    node_kernel<<<296, 128, node_smem>>>(ef, ea1, cut, W1, W2, ei);
    node0_kernel<<<296, 256, c0_smem>>>(attrs, Wsc0, out);
    node1_kernel<<<296, 256, c1_smem>>>(attrs, Wsc1, out);
}

// round 5
// speedup vs baseline: 1.1034x; 1.1034x over previous
#include <cuda_runtime.h>
#include <math.h>

#define NN 50000
#define EE 800000
#define CC 64
#define SS 10
#define HH 64

typedef unsigned long long ull;

// -------- scratch (static device globals; no allocation) --------
__device__ float g_h0[NN * CC];        // up-projected scalars   [n][c]
__device__ float g_h1[NN * 3 * CC];    // up-projected vectors   [n][i][c]
__device__ float g_T0[NN * CC];        // node messages (already /16)
__device__ float g_T1[NN * 3 * CC];
__device__ int   g_deg[NN];
__device__ int   g_off[NN + 1];
__device__ int   g_cur[NN];
__device__ int   g_perm[EE];

// -------- f32x2 packed math helpers (sm_100+) --------
__device__ __forceinline__ ull dup2(float x) {
    ull r;
    asm("mov.b64 %0, {%1, %1};" : "=l"(r) : "r"(__float_as_uint(x)));
    return r;
}
__device__ __forceinline__ void fma2(ull& d, ull a, ull b) {
    asm("fma.rn.f32x2 %0, %1, %2, %0;" : "+l"(d) : "l"(a), "l"(b));
}
__device__ __forceinline__ ull mul2(ull a, ull b) {
    ull d;
    asm("mul.rn.f32x2 %0, %1, %2;" : "=l"(d) : "l"(a), "l"(b));
    return d;
}
__device__ __forceinline__ void unpack2(ull v, float& lo, float& hi) {
    unsigned int a, b;
    asm("mov.b64 {%0, %1}, %2;" : "=r"(a), "=r"(b) : "l"(v));
    lo = __uint_as_float(a);
    hi = __uint_as_float(b);
}

// ============================================================
// CSR build
// ============================================================
__global__ void zero_deg_kernel() {
    int i = blockIdx.x * 256 + threadIdx.x;
    if (i < NN) g_deg[i] = 0;
}

__global__ void hist_kernel(const int* __restrict__ ei) {
    int e = blockIdx.x * 256 + threadIdx.x;   // E = 3125*256 exact
    atomicAdd(&g_deg[ei[EE + e]], 1);
}

__global__ void __launch_bounds__(1024) scan_kernel() {
    __shared__ int sp[1024];
    const int t = threadIdx.x;
    const int CH = (NN + 1023) / 1024;       // 49
    const int i0 = t * CH;
    const int i1 = min(i0 + CH, NN);
    int part = 0;
    for (int i = i0; i < i1; i++) part += g_deg[i];
    sp[t] = part;
    __syncthreads();
    for (int off = 1; off < 1024; off <<= 1) {
        int v = (t >= off) ? sp[t - off] : 0;
        __syncthreads();
        sp[t] += v;
        __syncthreads();
    }
    int run = sp[t] - part;                  // exclusive base
    for (int i = i0; i < i1; i++) {
        g_off[i] = run;
        g_cur[i] = run;
        run += g_deg[i];
    }
    if (t == 0) g_off[NN] = EE;
}

__global__ void scatter_kernel(const int* __restrict__ ei) {
    int e = blockIdx.x * 256 + threadIdx.x;
    int pos = atomicAdd(&g_cur[ei[EE + e]], 1);
    g_perm[pos] = e;
}

// ============================================================
// Up-projection: h0 = nf0 @ Wup0 ; g_h1[n][i][o] = sum_c nf1[n,c,i] Wup1[c,o]
// ============================================================
__global__ void __launch_bounds__(256) up_kernel(
    const float* __restrict__ nf0, const float* __restrict__ nf1,
    const float* __restrict__ Wup0, const float* __restrict__ Wup1) {
    extern __shared__ float sm[];
    float* sW0  = sm;            // 4096
    float* sW1m = sm + 4096;     // 4096
    float* s0   = sm + 8192;     // 32*64
    float* s1   = sm + 10240;    // 32*192
    const int tid  = threadIdx.x;
    const int base = blockIdx.x * 32;

    for (int i = tid; i < 4096; i += 256) { sW0[i] = Wup0[i]; sW1m[i] = Wup1[i]; }
    for (int i = tid; i < 2048; i += 256) {
        size_t g = (size_t)base * 64 + i;
        s0[i] = (g < (size_t)NN * 64) ? nf0[g] : 0.f;
    }
    for (int i = tid; i < 6144; i += 256) {
        size_t g = (size_t)base * 192 + i;
        s1[i] = (g < (size_t)NN * 192) ? nf1[g] : 0.f;
    }
    __syncthreads();

    const int o = tid & 63, ng = tid >> 6;
    for (int nl = ng; nl < 32; nl += 4) {
        const int n = base + nl;
        if (n >= NN) break;
        float a = 0.f;
#pragma unroll
        for (int c = 0; c < 64; c++) a += s0[nl * 64 + c] * sW0[c * 64 + o];
        g_h0[(size_t)n * 64 + o] = a;
#pragma unroll
        for (int i3 = 0; i3 < 3; i3++) {
            float b = 0.f;
#pragma unroll 16
            for (int c = 0; c < 64; c++)
                b += s1[nl * 192 + c * 3 + i3] * sW1m[c * 64 + o];
            g_h1[((size_t)n * 3 + i3) * 64 + o] = b;
        }
    }
}

// ============================================================
// Fused node-centric kernel: warp per node, NJ-edge batches.
// Gathers register-prefetched (first half before GEMV, second half
// issued before first combine). Hidden stored float2 in smem,
// W2 GEMV amortized over NJ edges. No atomics.
// ============================================================
__device__ __forceinline__ void gather4(
    const int src_, const int j0, ull* gh0, ull* ghx, ull* ghy, ull* ghz,
    const int l2) {
#pragma unroll
    for (int j = 0; j < 4; j++) {
        const int sj = __shfl_sync(0xffffffffu, src_, j0 + j);
        const float* p0 = g_h0 + (size_t)sj * 64 + l2;
        const float* p1 = g_h1 + (size_t)sj * 192 + l2;
        gh0[j] = *(const ull*)p0;
        ghx[j] = *(const ull*)p1;
        ghy[j] = *(const ull*)(p1 + 64);
        ghz[j] = *(const ull*)(p1 + 128);
    }
}

__device__ __forceinline__ void combine4(
    const float cu_, const float sx_, const float sy_, const float sz_,
    const int j0, const ull* gh0, const ull* ghx, const ull* ghy,
    const ull* ghz, const ull* w00, const ull* w11, const ull* w01,
    const ull* w10, ull& m0, ull& m1x, ull& m1y, ull& m1z) {
    const unsigned FULL = 0xffffffffu;
#pragma unroll
    for (int j = 0; j < 4; j++) {
        const float cub = __shfl_sync(FULL, cu_, j0 + j);
        const float sxb = __shfl_sync(FULL, sx_, j0 + j);
        const float syb = __shfl_sync(FULL, sy_, j0 + j);
        const float szb = __shfl_sync(FULL, sz_, j0 + j);
        ull d = mul2(ghx[j], dup2(sxb));
        fma2(d, ghy[j], dup2(syb));
        fma2(d, ghz[j], dup2(szb));
        ull t = mul2(w00[j0 + j], gh0[j]);
        fma2(t, w11[j0 + j], d);
        fma2(m0, t, dup2(cub));
        ull p = mul2(w01[j0 + j], gh0[j]);
        fma2(m1x, p, dup2(cub * sxb));
        fma2(m1y, p, dup2(cub * syb));
        fma2(m1z, p, dup2(cub * szb));
        ull q = mul2(w10[j0 + j], dup2(cub));
        fma2(m1x, q, ghx[j]);
        fma2(m1y, q, ghy[j]);
        fma2(m1z, q, ghz[j]);
    }
}

template<int NJ>
__device__ __forceinline__ void process_batch(
    const int b, const int end, const int lane,
    const float* __restrict__ sW1, const float* __restrict__ sW2,
    float* __restrict__ sH,
    const float* __restrict__ ef, const float* __restrict__ ea1,
    const float* __restrict__ cut, const int* __restrict__ ei,
    ull& m0, ull& m1x, ull& m1y, ull& m1z) {
    const unsigned FULL = 0xffffffffu;
    const int l2 = 2 * lane;

    // lanes 0..NJ-1 stage edge b+lane (padded slots: cu=0 kills contributions)
    int src_ = 0;
    float cu_ = 0.f, sx_ = 0.f, sy_ = 0.f, sz_ = 0.f;
    float4 f0_ = make_float4(0.f, 0.f, 0.f, 0.f), f1_ = f0_;
    if (lane < NJ) {
        const int idx = b + lane;
        const int ee  = g_perm[idx < end ? idx : b];
        src_ = ei[ee];
        cu_  = (idx < end) ? cut[ee] : 0.f;
        sx_  = ea1[ee * 3];
        sy_  = ea1[ee * 3 + 1];
        sz_  = ea1[ee * 3 + 2];
        f0_  = *(const float4*)(ef + (size_t)ee * 8);
        f1_  = *(const float4*)(ef + (size_t)ee * 8 + 4);
    }

    // hidden = silu(ef @ W1); lane computes units (2l, 2l+1) per edge
#pragma unroll
    for (int j = 0; j < NJ; j++) {
        float fr[8];
        fr[0] = __shfl_sync(FULL, f0_.x, j);
        fr[1] = __shfl_sync(FULL, f0_.y, j);
        fr[2] = __shfl_sync(FULL, f0_.z, j);
        fr[3] = __shfl_sync(FULL, f0_.w, j);
        fr[4] = __shfl_sync(FULL, f1_.x, j);
        fr[5] = __shfl_sync(FULL, f1_.y, j);
        fr[6] = __shfl_sync(FULL, f1_.z, j);
        fr[7] = __shfl_sync(FULL, f1_.w, j);
        float a0 = 0.f, a1 = 0.f;
#pragma unroll
        for (int r = 0; r < 8; r++) {
            float2 wv = *(const float2*)(sW1 + r * 64 + l2);
            a0 = fmaf(fr[r], wv.x, a0);
            a1 = fmaf(fr[r], wv.y, a1);
        }
        a0 = a0 / (1.f + __expf(-a0));
        a1 = a1 / (1.f + __expf(-a1));
        *(float2*)(sH + j * 64 + l2) = make_float2(a0, a1);
    }
    __syncwarp();

    // prefetch gathers for first half (hidden under the GEMV below)
    ull gh0a[4], ghxa[4], ghya[4], ghza[4];
    gather4(src_, 0, gh0a, ghxa, ghya, ghza, l2);

    // w = hid @ W2; lane owns channel pair (2l, 2l+1) of each of 4 groups
    ull w00[NJ], w11[NJ], w01[NJ], w10[NJ];
#pragma unroll
    for (int j = 0; j < NJ; j++) { w00[j] = 0; w11[j] = 0; w01[j] = 0; w10[j] = 0; }
    const float* bp = sW2 + l2;
#pragma unroll 1
    for (int h = 0; h < 64; h += 2) {
        const float* r0 = bp + h * 256;
        const float* r1 = r0 + 256;
        const ull b00a = *(const ull*)r0,         b00b = *(const ull*)r1;
        const ull b11a = *(const ull*)(r0 + 64),  b11b = *(const ull*)(r1 + 64);
        const ull b01a = *(const ull*)(r0 + 128), b01b = *(const ull*)(r1 + 128);
        const ull b10a = *(const ull*)(r0 + 192), b10b = *(const ull*)(r1 + 192);
#pragma unroll
        for (int j = 0; j < NJ; j++) {
            const float2 hv = *(const float2*)(sH + j * 64 + h);  // broadcast
            const ull ha = dup2(hv.x), hb = dup2(hv.y);
            fma2(w00[j], ha, b00a); fma2(w00[j], hb, b00b);
            fma2(w11[j], ha, b11a); fma2(w11[j], hb, b11b);
            fma2(w01[j], ha, b01a); fma2(w01[j], hb, b01b);
            fma2(w10[j], ha, b10a); fma2(w10[j], hb, b10b);
        }
    }

    if constexpr (NJ == 8) {
        // prefetch second half; its latency hides under first combine
        ull gh0b[4], ghxb[4], ghyb[4], ghzb[4];
        gather4(src_, 4, gh0b, ghxb, ghyb, ghzb, l2);
        combine4(cu_, sx_, sy_, sz_, 0, gh0a, ghxa, ghya, ghza,
                 w00, w11, w01, w10, m0, m1x, m1y, m1z);
        combine4(cu_, sx_, sy_, sz_, 4, gh0b, ghxb, ghyb, ghzb,
                 w00, w11, w01, w10, m0, m1x, m1y, m1z);
    } else {
        combine4(cu_, sx_, sy_, sz_, 0, gh0a, ghxa, ghya, ghza,
                 w00, w11, w01, w10, m0, m1x, m1y, m1z);
    }
    __syncwarp();   // protect sH before next batch overwrites
}

__global__ void __launch_bounds__(128, 3) node_kernel(
    const float* __restrict__ ef, const float* __restrict__ ea1,
    const float* __restrict__ cut, const float* __restrict__ W1,
    const float* __restrict__ W2, const int* __restrict__ ei) {
    extern __shared__ float sm[];
    float* sW1 = sm;                           // 512 floats
    float* sW2 = sm + 512;                     // 16384 floats
    float* sHAll = sm + 512 + 16384;           // 4 warps * 512 floats
    const int tid = threadIdx.x;
    for (int i = tid; i < 512; i += 128)   sW1[i] = W1[i];
    for (int i = tid; i < 16384; i += 128) sW2[i] = W2[i];
    __syncthreads();

    const int wid = tid >> 5, lane = tid & 31;
    float* sH = sHAll + wid * 512;
    const int l2 = 2 * lane;

    for (int node = blockIdx.x * 4 + wid; node < NN; node += gridDim.x * 4) {
        const int beg = g_off[node];
        const int end = g_off[node + 1];
        ull m0 = 0, m1x = 0, m1y = 0, m1z = 0;

        int b = beg;
        for (; b + 8 <= end; b += 8)
            process_batch<8>(b, end, lane, sW1, sW2, sH, ef, ea1, cut, ei,
                             m0, m1x, m1y, m1z);
        const int rem = end - b;
        if (rem > 4)
            process_batch<8>(b, end, lane, sW1, sW2, sH, ef, ea1, cut, ei,
                             m0, m1x, m1y, m1z);
        else if (rem > 0)
            process_batch<4>(b, end, lane, sW1, sW2, sH, ef, ea1, cut, ei,
                             m0, m1x, m1y, m1z);

        const ull inv = dup2(1.f / 16.f);
        *(ull*)(g_T0 + (size_t)node * 64 + l2) = mul2(m0, inv);
        float* t1 = g_T1 + (size_t)node * 192 + l2;
        *(ull*)t1         = mul2(m1x, inv);
        *(ull*)(t1 + 64)  = mul2(m1y, inv);
        *(ull*)(t1 + 128) = mul2(m1z, inv);
    }
}

// ============================================================
// Epilogue 0: out[n][0:64] = mi0 ; out[n][256:320] = mi0 @ Wsc0[s]
// ============================================================
__global__ void __launch_bounds__(256) node0_kernel(
    const float* __restrict__ attrs, const float* __restrict__ Wsc0,
    float* __restrict__ out) {
    extern __shared__ float sm[];
    float* sW  = sm;              // 40960
    float* sMi = sm + 40960;      // 8 warps * 64
    const int tid = threadIdx.x, wid = tid >> 5, lane = tid & 31;
    const int l2 = 2 * lane;
    const unsigned FULL = 0xffffffffu;
    for (int i = tid; i < SS * CC * CC; i += 256) sW[i] = Wsc0[i];
    __syncthreads();

    float* sMiW = sMi + wid * 64;
    for (int node = blockIdx.x * 8 + wid; node < NN; node += gridDim.x * 8) {
        const ull mi = *(const ull*)(g_T0 + (size_t)node * 64 + l2);
        *(ull*)(sMiW + l2) = mi;
        const float av = (lane < SS) ? attrs[(size_t)node * SS + lane] : 0.f;
        const unsigned bal = __ballot_sync(FULL, av > 0.5f);
        int s = __ffs(bal) - 1;
        if (s < 0) s = 0;
        __syncwarp();
        const float* W = sW + s * 4096 + l2;
        ull A = 0;
#pragma unroll 8
        for (int c = 0; c < 64; c++)
            fma2(A, dup2(sMiW[c]), *(const ull*)(W + c * 64));
        float* orow = out + (size_t)node * 512;
        *(ull*)(orow + l2)       = mi;
        *(ull*)(orow + 256 + l2) = A;
        __syncwarp();
    }
}

// ============================================================
// Epilogue 1: out[n][64+c*3+i] = mi1 ; out[n][320+o*3+i] = res1
// ============================================================
__global__ void __launch_bounds__(256) node1_kernel(
    const float* __restrict__ attrs, const float* __restrict__ Wsc1,
    float* __restrict__ out) {
    extern __shared__ float sm[];
    float* sW  = sm;              // 40960
    float* sMi = sm + 40960;      // 8 warps * 192
    const int tid = threadIdx.x, wid = tid >> 5, lane = tid & 31;
    const int l2 = 2 * lane;
    const unsigned FULL = 0xffffffffu;
    for (int i = tid; i < SS * CC * CC; i += 256) sW[i] = Wsc1[i];
    __syncthreads();

    float* sMiW = sMi + wid * 192;
    for (int node = blockIdx.x * 8 + wid; node < NN; node += gridDim.x * 8) {
        const float* t1 = g_T1 + (size_t)node * 192 + l2;
        const ull mx = *(const ull*)t1;
        const ull my = *(const ull*)(t1 + 64);
        const ull mz = *(const ull*)(t1 + 128);
        *(ull*)(sMiW + l2)        = mx;
        *(ull*)(sMiW + 64 + l2)   = my;
        *(ull*)(sMiW + 128 + l2)  = mz;
        const float av = (lane < SS) ? attrs[(size_t)node * SS + lane] : 0.f;
        const unsigned bal = __ballot_sync(FULL, av > 0.5f);
        int s = __ffs(bal) - 1;
        if (s < 0) s = 0;
        __syncwarp();
        const float* W = sW + s * 4096 + l2;
        ull A0 = 0, A1 = 0, A2 = 0;
#pragma unroll 8
        for (int c = 0; c < 64; c++) {
            const ull wv = *(const ull*)(W + c * 64);
            fma2(A0, dup2(sMiW[c]), wv);
            fma2(A1, dup2(sMiW[64 + c]), wv);
            fma2(A2, dup2(sMiW[128 + c]), wv);
        }
        float x0, x1, y0, y1, z0, z1;
        unpack2(mx, x0, x1); unpack2(my, y0, y1); unpack2(mz, z0, z1);
        float* orow = out + (size_t)node * 512;
        float* om = orow + 64 + 6 * lane;
        om[0] = x0; om[1] = y0; om[2] = z0;
        om[3] = x1; om[4] = y1; om[5] = z1;
        unpack2(A0, x0, x1); unpack2(A1, y0, y1); unpack2(A2, z0, z1);
        float* orr = orow + 320 + 6 * lane;
        orr[0] = x0; orr[1] = y0; orr[2] = z0;
        orr[3] = x1; orr[4] = y1; orr[5] = z1;
        __syncwarp();
    }
}

// ============================================================
extern "C" void kernel_launch(void* const* d_in, const int* in_sizes, int n_in,
                              void* d_out, int out_size) {
    const float* nf0   = (const float*)d_in[0];
    const float* nf1   = (const float*)d_in[1];
    const float* attrs = (const float*)d_in[2];
    const float* ef    = (const float*)d_in[3];
    const float* ea1   = (const float*)d_in[4];
    const float* cut   = (const float*)d_in[5];
    const float* Wup0  = (const float*)d_in[6];
    const float* Wup1  = (const float*)d_in[7];
    const float* W1    = (const float*)d_in[8];
    const float* W2    = (const float*)d_in[9];
    const float* Wsc0  = (const float*)d_in[10];
    const float* Wsc1  = (const float*)d_in[11];
    // d_in[12], d_in[13] are Q0/Q1 identity projectors (no-op)
    const int*   ei    = (const int*)d_in[14];
    float* out = (float*)d_out;

    const int up_smem   = 16384 * 4;                        // 64 KB
    const int node_smem = (512 + 16384 + 2048) * 4;         // 75.8 KB -> 3 CTA/SM
    const int c0_smem   = (40960 + 512) * 4;                // 166 KB
    const int c1_smem   = (40960 + 1536) * 4;               // 170 KB
    cudaFuncSetAttribute(up_kernel,    cudaFuncAttributeMaxDynamicSharedMemorySize, up_smem);
    cudaFuncSetAttribute(node_kernel,  cudaFuncAttributeMaxDynamicSharedMemorySize, node_smem);
    cudaFuncSetAttribute(node0_kernel, cudaFuncAttributeMaxDynamicSharedMemorySize, c0_smem);
    cudaFuncSetAttribute(node1_kernel, cudaFuncAttributeMaxDynamicSharedMemorySize, c1_smem);

    zero_deg_kernel<<<(NN + 255) / 256, 256>>>();
    hist_kernel<<<EE / 256, 256>>>(ei);
    scan_kernel<<<1, 1024>>>();
    scatter_kernel<<<EE / 256, 256>>>(ei);
    up_kernel<<<(NN + 31) / 32, 256, up_smem>>>(nf0, nf1, Wup0, Wup1);
    node_kernel<<<444, 128, node_smem>>>(ef, ea1, cut, W1, W2, ei);
    node0_kernel<<<296, 256, c0_smem>>>(attrs, Wsc0, out);
    node1_kernel<<<296, 256, c1_smem>>>(attrs, Wsc1, out);
}